// round 11
// baseline (speedup 1.0000x reference)
#include <cuda_runtime.h>
#include <cstdint>

#define NBAS  2048
#define TT    4015
#define CH    32
// chunks 0..124 full (t=0..3999), chunk 125 = 15-step tail (t=4000..4014)

__device__ __forceinline__ float sqrt_ap(float x){ float y; asm("sqrt.approx.f32 %0, %1;" : "=f"(y) : "f"(x)); return y; }
__device__ __forceinline__ float rsqrt_ap(float x){ float y; asm("rsqrt.approx.f32 %0, %1;" : "=f"(y) : "f"(x)); return y; }

// Named barriers, 2 participating warps each (count = 64).
__device__ __forceinline__ void bsync(int id){ asm volatile("bar.sync %0, 64;" :: "r"(id)); }
__device__ __forceinline__ void barr(int id){ asm volatile("bar.arrive %0, 64;" :: "r"(id)); }
// ids: FULL_P = 1+(k&1), FREE_P = 3+(k&1), FULL_Q = 5+(k&1), FREE_Q = 7+(k&1)

__device__ __forceinline__ void cpa8(uint32_t saddr, const void* g){
  asm volatile("cp.async.ca.shared.global [%0], [%1], 8;" :: "r"(saddr), "l"(g));
}
__device__ __forceinline__ void cpa_commit(){ asm volatile("cp.async.commit_group;"); }
template<int N>
__device__ __forceinline__ void cpa_wait(){ asm volatile("cp.async.wait_group %0;" :: "n"(N)); }

__shared__ float2 pebuf[2][CH][32];   // 16 KB  (W0 private)
__shared__ float  prbuf[2][CH][32];   //  8 KB  (W0 -> W1)
__shared__ float2 qbuf [2][CH][32];   // 16 KB  (W1 -> W2)

// ---------------- production (W0) ----------------
// tanh(x) ~ x for x <= 0.01; 1/(1+d) ~ 1-d+d^2, d <= 0.01;
// (1+y)^(-1/4), y <= 0.039 -> 4-term Taylor. s2 clip provably inactive.
struct PSt { float s, inv_x1, c49; };

__device__ __forceinline__ float prod_step(PSt& st, float2 pe){
  float diff = pe.x - pe.y;
  float pn = fmaxf(diff, 0.f);
  float en = fmaxf(-diff, 0.f);
  float xp = pn * st.inv_x1;
  float xe = en * st.inv_x1;
  float u  = st.s * st.inv_x1;
  float dp = u * xp;
  float ip = fmaf(dp, dp - 1.f, 1.f);
  float ps = pn * fmaf(-u, u, 1.f) * ip;
  float de = (1.f - u) * xe;
  float ie = fmaf(de, de - 1.f, 1.f);
  float es = st.s * (2.f - u) * xe * ie;
  float s2 = (st.s - es) + ps;
  float m  = s2 * st.c49;
  float m2 = m * m;
  float y  = m2 * m2;
  float p  = fmaf(y, fmaf(y, -15.f/128.f, 5.f/32.f), -0.25f);
  float w  = fmaf(y, p, 1.f);
  float snew = s2 * w;
  float pr = (s2 - snew) + (pn - ps);
  st.s = snew;
  return pr;
}

// ---------------- conv (W1) ----------------
struct CSt {
  float u10,u11,u12, u20,u21,u22,u23,u24,u25;
  float h1,h2,h3,h4,h5;
};

__device__ __forceinline__ float2 conv_step(CSt& st, float pr){
  float q9 = st.u10*pr + st.u11*st.h1 + st.u12*st.h2;
  float q1 = st.u20*pr + st.u21*st.h1 + st.u22*st.h2
           + st.u23*st.h3 + st.u24*st.h4 + st.u25*st.h5;
  st.h5 = st.h4; st.h4 = st.h3; st.h3 = st.h2; st.h2 = st.h1; st.h1 = pr;
  return make_float2(q9, q1);
}

// ---------------- routing (W2): pure recurrence ----------------
// Loop state: r and csq = c35 * sqrt(r). The sqrt for the NEXT step is issued
// right after rn is formed (off the critical chain); gex is then FMA-only.
template<int NSTEP, int STORE_FROM>
__device__ __forceinline__ float* route_chunk(float& r, float& csq,
                                              const float2* qb,
                                              float c35, float ix3_4, float* op){
  float2 qv[4];
  qv[0] = qb[0];
  if (NSTEP > 1) qv[1] = qb[32];
  if (NSTEP > 2) qv[2] = qb[64];
  if (NSTEP > 3) qv[3] = qb[96];
  #pragma unroll
  for (int j = 0; j < NSTEP; j++){
    float q9 = qv[j & 3].x, q1 = qv[j & 3].y;
    if (j + 4 < NSTEP) qv[j & 3] = qb[(j + 4) * 32];
    float r2  = r * r;
    float r3  = r2 * r;
    float gex = r3 * csq;                    // c35 * r^3.5, sqrt carried in
    float rr  = fmaxf((r + q9) + gex, 0.f);
    float t2  = rr * rr;
    float t4  = t2 * t2;
    float a   = fmaf(t4, ix3_4, 1.f);
    float w   = rsqrt_ap(sqrt_ap(a));
    float rn  = rr * w;
    float sqn = sqrt_ap(rn);                 // off-chain: for NEXT step's gex
    r   = rn;
    csq = c35 * sqn;
    if (j >= STORE_FROM){
      *op = (rr - rn) + fmaxf(q1 + gex, 0.f);
      op += NBAS;
    }
  }
  return op;
}

__global__ void __launch_bounds__(96)
gr4j_3w(const float2* __restrict__ pe, const float4* __restrict__ prm,
        float* __restrict__ out){
  int lane = threadIdx.x & 31;
  int wid  = threadIdx.x >> 5;
  int b    = blockIdx.x * 32 + lane;
  float4 pm = prm[b];

  if (wid == 0){
    // ============== W0: loads + production ==============
    PSt st;
    float x1 = fmaf(pm.x, 1100.f, 100.f);
    st.inv_x1 = 1.f / x1;
    st.c49 = (4.f/9.f) * st.inv_x1;
    st.s = 0.5f * x1;

    const char* gb = (const char*)(pe + b);
    auto issue_chunk = [&](int k){
      int buf = k & 1;
      uint32_t sbase = (uint32_t)__cvta_generic_to_shared(&pebuf[buf][0][lane]);
      int tb = k * CH;
      #pragma unroll 8
      for (int j = 0; j < CH; j++){
        int tt = tb + j; tt = tt < TT ? tt : TT - 1;
        cpa8(sbase + j * 32 * 8, gb + (size_t)tt * (NBAS * 8));
      }
      cpa_commit();
    };

    issue_chunk(0);
    issue_chunk(1);

    for (int k = 0; k < 125; k++){
      if (k >= 2) bsync(3 + (k & 1));
      cpa_wait<1>();
      int buf = k & 1;
      #pragma unroll 8
      for (int j = 0; j < CH; j++){
        prbuf[buf][j][lane] = prod_step(st, pebuf[buf][j][lane]);
      }
      barr(1 + (k & 1));
      if (k + 2 <= 125) issue_chunk(k + 2);
    }
    // tail (chunk 125, buf 1, 15 steps)
    bsync(3 + 1);
    cpa_wait<0>();
    #pragma unroll 8
    for (int j = 0; j < 15; j++){
      prbuf[1][j][lane] = prod_step(st, pebuf[1][j][lane]);
    }
    barr(1 + 1);
  } else if (wid == 1){
    // ============== W1: FIR conv ==============
    CSt st;
    float x4 = fmaf(pm.w, 1.8f, 1.1f);
    float ix4 = 1.f / x4;
    float sh1[4], sh2[7];
    #pragma unroll
    for (int t = 0; t < 4; t++){
      float a = fminf((float)t * ix4, 1.f);
      sh1[t] = a * a * sqrtf(a);
    }
    #pragma unroll
    for (int t = 0; t < 7; t++){
      float rr = (float)t * ix4; float v;
      if ((float)t <= x4){ v = 0.5f * rr * rr * sqrtf(rr); }
      else { float mm = fmaxf(2.f - rr, 0.f); v = 1.f - 0.5f * mm * mm * sqrtf(mm); }
      sh2[t] = v;
    }
    st.u10 = sh1[1]-sh1[0]; st.u11 = sh1[2]-sh1[1]; st.u12 = sh1[3]-sh1[2];
    st.u20 = sh2[1]-sh2[0]; st.u21 = sh2[2]-sh2[1]; st.u22 = sh2[3]-sh2[2];
    st.u23 = sh2[4]-sh2[3]; st.u24 = sh2[5]-sh2[4]; st.u25 = sh2[6]-sh2[5];
    st.h1=0.f; st.h2=0.f; st.h3=0.f; st.h4=0.f; st.h5=0.f;

    for (int k = 0; k < 125; k++){
      bsync(1 + (k & 1));                 // pr chunk ready
      if (k >= 2) bsync(7 + (k & 1));     // q buffer free
      int buf = k & 1;
      if (k == 11){
        #pragma unroll 8
        for (int j = 0; j < 13; j++) qbuf[buf][j][lane] = conv_step(st, prbuf[buf][j][lane]);
        st.h1=0.f; st.h2=0.f; st.h3=0.f; st.h4=0.f; st.h5=0.f;   // reset before t=365
        #pragma unroll 8
        for (int j = 13; j < CH; j++) qbuf[buf][j][lane] = conv_step(st, prbuf[buf][j][lane]);
      } else {
        #pragma unroll 8
        for (int j = 0; j < CH; j++) qbuf[buf][j][lane] = conv_step(st, prbuf[buf][j][lane]);
      }
      barr(5 + (k & 1));                  // q chunk ready
      barr(3 + (k & 1));                  // pr buffer free
    }
    // tail
    bsync(1 + 1);
    bsync(7 + 1);
    #pragma unroll 8
    for (int j = 0; j < 15; j++) qbuf[1][j][lane] = conv_step(st, prbuf[1][j][lane]);
    barr(5 + 1);
  } else {
    // ============== W2: routing only ==============
    float x2 = fmaf(pm.y,   8.f,  -5.f);
    float x3 = fmaf(pm.z, 280.f,  20.f);
    float ix3 = 1.f / x3;
    float i2  = ix3 * ix3;
    float c35   = x2 * (ix3 * ix3 * ix3) * sqrtf(ix3);
    float ix3_4 = i2 * i2;
    float r   = 0.5f * x3;
    float csq = c35 * sqrtf(r);

    float* op = out + b;

    // chunks 0..10: t = 0..351, no stores
    for (int k = 0; k < 11; k++){
      bsync(5 + (k & 1));
      route_chunk<CH, CH>(r, csq, &qbuf[k & 1][0][lane], c35, ix3_4, nullptr);
      barr(7 + (k & 1));
    }
    // chunk 11 (buf 1): store from j=13 (t=365 -> ti=0)
    {
      bsync(5 + 1);
      op = route_chunk<CH, 13>(r, csq, &qbuf[1][0][lane], c35, ix3_4, op);
      barr(7 + 1);
    }
    // chunks 12..124: all store
    for (int k = 12; k < 125; k++){
      bsync(5 + (k & 1));
      op = route_chunk<CH, 0>(r, csq, &qbuf[k & 1][0][lane], c35, ix3_4, op);
      barr(7 + (k & 1));
    }
    // tail (15 steps -> ti 3635..3649)
    bsync(5 + 1);
    route_chunk<15, 0>(r, csq, &qbuf[1][0][lane], c35, ix3_4, op);
  }
}

extern "C" void kernel_launch(void* const* d_in, const int* in_sizes, int n_in,
                              void* d_out, int out_size){
  const void* a = d_in[0];
  const void* c = d_in[1];
  const float2* pe;
  const float4* prm;
  if (in_sizes[0] > in_sizes[1]) { pe = (const float2*)a; prm = (const float4*)c; }
  else                           { pe = (const float2*)c; prm = (const float4*)a; }
  gr4j_3w<<<NBAS / 32, 96>>>(pe, prm, (float*)d_out);
}

// round 15
// speedup vs baseline: 1.0634x; 1.0634x over previous
#include <cuda_runtime.h>
#include <cstdint>

#define NBAS  2048
#define TT    4015
#define CH    32
// chunks 0..124 full (t=0..3999), chunk 125 = 15-step tail (t=4000..4014)

__device__ __forceinline__ float sqrt_ap(float x){ float y; asm("sqrt.approx.f32 %0, %1;" : "=f"(y) : "f"(x)); return y; }
__device__ __forceinline__ float rsqrt_ap(float x){ float y; asm("rsqrt.approx.f32 %0, %1;" : "=f"(y) : "f"(x)); return y; }

// Named barriers, 2 participating warps each (count = 64).
__device__ __forceinline__ void bsync(int id){ asm volatile("bar.sync %0, 64;" :: "r"(id)); }
__device__ __forceinline__ void barr(int id){ asm volatile("bar.arrive %0, 64;" :: "r"(id)); }
// ids: FULL_P = 1+(k&1), FREE_P = 3+(k&1), FULL_Q = 5+(k&1), FREE_Q = 7+(k&1)
// FREE_Q(k) now additionally means "chunk k's q values are written back into qbuf".

__device__ __forceinline__ void cpa8(uint32_t saddr, const void* g){
  asm volatile("cp.async.ca.shared.global [%0], [%1], 8;" :: "r"(saddr), "l"(g));
}
__device__ __forceinline__ void cpa_commit(){ asm volatile("cp.async.commit_group;"); }
template<int N>
__device__ __forceinline__ void cpa_wait(){ asm volatile("cp.async.wait_group %0;" :: "n"(N)); }

__shared__ float2 pebuf[2][CH][32];   // 16 KB  (W0 private)
__shared__ float  prbuf[2][CH][32];   //  8 KB  (W0 -> W1)
__shared__ float2 qbuf [2][CH][32];   // 16 KB  (W1 -> W2: q9,q1; W2 -> W1: q in .x)

// ---------------- production (W0) ----------------
struct PSt { float s, inv_x1, c49; };

__device__ __forceinline__ float prod_step(PSt& st, float2 pe){
  float diff = pe.x - pe.y;
  float pn = fmaxf(diff, 0.f);
  float en = fmaxf(-diff, 0.f);
  float xp = pn * st.inv_x1;
  float xe = en * st.inv_x1;
  float u  = st.s * st.inv_x1;
  float dp = u * xp;
  float ip = fmaf(dp, dp - 1.f, 1.f);
  float ps = pn * fmaf(-u, u, 1.f) * ip;
  float de = (1.f - u) * xe;
  float ie = fmaf(de, de - 1.f, 1.f);
  float es = st.s * (2.f - u) * xe * ie;
  float s2 = (st.s - es) + ps;
  float m  = s2 * st.c49;
  float m2 = m * m;
  float y  = m2 * m2;
  float p  = fmaf(y, fmaf(y, -15.f/128.f, 5.f/32.f), -0.25f);
  float w  = fmaf(y, p, 1.f);
  float snew = s2 * w;
  float pr = (s2 - snew) + (pn - ps);
  st.s = snew;
  return pr;
}

// ---------------- conv (W1) ----------------
struct CSt {
  float u10,u11,u12, u20,u21,u22,u23,u24,u25;
  float h1,h2,h3,h4,h5;
};

__device__ __forceinline__ float2 conv_step(CSt& st, float pr){
  float q9 = st.u10*pr + st.u11*st.h1 + st.u12*st.h2;
  float q1 = st.u20*pr + st.u21*st.h1 + st.u22*st.h2
           + st.u23*st.h3 + st.u24*st.h4 + st.u25*st.h5;
  st.h5 = st.h4; st.h4 = st.h3; st.h3 = st.h2; st.h2 = st.h1; st.h1 = pr;
  return make_float2(q9, q1);
}

// ---------------- routing (W2): pure recurrence, STS writeback ----------------
// Loop state: r and csq = c35 * sqrt(r); next-step sqrt issued off-chain.
// q is written back in-place to qbuf[...][j].x via STS (W1 flushes to GMEM).
template<int NSTEP>
__device__ __forceinline__ void route_chunk(float& r, float& csq, float2* qb,
                                            float c35, float ix3_4){
  float2 qv[4];
  qv[0] = qb[0];
  if (NSTEP > 1) qv[1] = qb[32];
  if (NSTEP > 2) qv[2] = qb[64];
  if (NSTEP > 3) qv[3] = qb[96];
  #pragma unroll
  for (int j = 0; j < NSTEP; j++){
    float q9 = qv[j & 3].x, q1 = qv[j & 3].y;
    if (j + 4 < NSTEP) qv[j & 3] = qb[(j + 4) * 32];
    float r2  = r * r;
    float r3  = r2 * r;
    float gex = r3 * csq;                    // c35 * r^3.5 (sqrt carried)
    float rr  = fmaxf((r + q9) + gex, 0.f);
    float t2  = rr * rr;
    float t4  = t2 * t2;
    float a   = fmaf(t4, ix3_4, 1.f);
    float w   = rsqrt_ap(sqrt_ap(a));
    float rn  = rr * w;
    float sqn = sqrt_ap(rn);                 // off-chain, for next step
    r   = rn;
    csq = c35 * sqn;
    qb[j * 32].x = (rr - rn) + fmaxf(q1 + gex, 0.f);   // STS.32, imm offset
  }
}

__global__ void __launch_bounds__(96)
gr4j_3w(const float2* __restrict__ pe, const float4* __restrict__ prm,
        float* __restrict__ out){
  int lane = threadIdx.x & 31;
  int wid  = threadIdx.x >> 5;
  int b    = blockIdx.x * 32 + lane;
  float4 pm = prm[b];

  if (wid == 0){
    // ============== W0: loads + production ==============
    PSt st;
    float x1 = fmaf(pm.x, 1100.f, 100.f);
    st.inv_x1 = 1.f / x1;
    st.c49 = (4.f/9.f) * st.inv_x1;
    st.s = 0.5f * x1;

    const char* gb = (const char*)(pe + b);
    auto issue_chunk = [&](int k){
      int buf = k & 1;
      uint32_t sbase = (uint32_t)__cvta_generic_to_shared(&pebuf[buf][0][lane]);
      int tb = k * CH;
      #pragma unroll 8
      for (int j = 0; j < CH; j++){
        int tt = tb + j; tt = tt < TT ? tt : TT - 1;
        cpa8(sbase + j * 32 * 8, gb + (size_t)tt * (NBAS * 8));
      }
      cpa_commit();
    };

    issue_chunk(0);
    issue_chunk(1);

    for (int k = 0; k < 125; k++){
      if (k >= 2) bsync(3 + (k & 1));
      cpa_wait<1>();
      int buf = k & 1;
      #pragma unroll 8
      for (int j = 0; j < CH; j++){
        prbuf[buf][j][lane] = prod_step(st, pebuf[buf][j][lane]);
      }
      barr(1 + (k & 1));
      if (k + 2 <= 125) issue_chunk(k + 2);
    }
    // tail (chunk 125, buf 1, 15 steps)
    bsync(3 + 1);
    cpa_wait<0>();
    #pragma unroll 8
    for (int j = 0; j < 15; j++){
      prbuf[1][j][lane] = prod_step(st, pebuf[1][j][lane]);
    }
    barr(1 + 1);
  } else if (wid == 1){
    // ============== W1: FIR conv + GMEM store flush ==============
    CSt st;
    float x4 = fmaf(pm.w, 1.8f, 1.1f);
    float ix4 = 1.f / x4;
    float sh1[4], sh2[7];
    #pragma unroll
    for (int t = 0; t < 4; t++){
      float a = fminf((float)t * ix4, 1.f);
      sh1[t] = a * a * sqrtf(a);
    }
    #pragma unroll
    for (int t = 0; t < 7; t++){
      float rr = (float)t * ix4; float v;
      if ((float)t <= x4){ v = 0.5f * rr * rr * sqrtf(rr); }
      else { float mm = fmaxf(2.f - rr, 0.f); v = 1.f - 0.5f * mm * mm * sqrtf(mm); }
      sh2[t] = v;
    }
    st.u10 = sh1[1]-sh1[0]; st.u11 = sh1[2]-sh1[1]; st.u12 = sh1[3]-sh1[2];
    st.u20 = sh2[1]-sh2[0]; st.u21 = sh2[2]-sh2[1]; st.u22 = sh2[3]-sh2[2];
    st.u23 = sh2[4]-sh2[3]; st.u24 = sh2[5]-sh2[4]; st.u25 = sh2[6]-sh2[5];
    st.h1=0.f; st.h2=0.f; st.h3=0.f; st.h4=0.f; st.h5=0.f;

    // flush chunk c's q values (written by W2 into qbuf[c&1][j][lane].x)
    auto flush = [&](int c, int nstep){
      int buf = c & 1;
      int t0  = c * CH;
      if (t0 + nstep <= 365) return;           // entirely warmup
      for (int j = 0; j < nstep; j++){
        int t = t0 + j;
        if (t >= 365){
          out[(t - 365) * NBAS + b] = qbuf[buf][j][lane].x;
        }
      }
    };

    for (int k = 0; k < 126; k++){
      int nstep = (k == 125) ? 15 : CH;
      bsync(1 + (k & 1));                 // pr chunk ready
      if (k >= 2){
        bsync(7 + (k & 1));               // W2 done with buf (chunk k-2), q written
        flush(k - 2, CH);
      }
      int buf = k & 1;
      if (k == 11){
        for (int j = 0; j < 13; j++) qbuf[buf][j][lane] = conv_step(st, prbuf[buf][j][lane]);
        st.h1=0.f; st.h2=0.f; st.h3=0.f; st.h4=0.f; st.h5=0.f;   // reset before t=365
        for (int j = 13; j < CH; j++) qbuf[buf][j][lane] = conv_step(st, prbuf[buf][j][lane]);
      } else {
        #pragma unroll 8
        for (int j = 0; j < nstep; j++) qbuf[buf][j][lane] = conv_step(st, prbuf[buf][j][lane]);
      }
      barr(5 + (k & 1));                  // q9/q1 chunk ready
      barr(3 + (k & 1));                  // pr buffer free
    }
    // drain: chunks 124 (even) and 125 (odd) still unflushed
    bsync(7 + 0);
    flush(124, CH);
    bsync(7 + 1);
    flush(125, 15);
  } else {
    // ============== W2: routing only ==============
    float x2 = fmaf(pm.y,   8.f,  -5.f);
    float x3 = fmaf(pm.z, 280.f,  20.f);
    float ix3 = 1.f / x3;
    float i2  = ix3 * ix3;
    float c35   = x2 * (ix3 * ix3 * ix3) * sqrtf(ix3);
    float ix3_4 = i2 * i2;
    float r   = 0.5f * x3;
    float csq = c35 * sqrtf(r);

    for (int k = 0; k < 125; k++){
      bsync(5 + (k & 1));
      route_chunk<CH>(r, csq, &qbuf[k & 1][0][lane], c35, ix3_4);
      barr(7 + (k & 1));
    }
    // tail (15 steps)
    bsync(5 + 1);
    route_chunk<15>(r, csq, &qbuf[1][0][lane], c35, ix3_4);
    barr(7 + 1);
  }
}

extern "C" void kernel_launch(void* const* d_in, const int* in_sizes, int n_in,
                              void* d_out, int out_size){
  const void* a = d_in[0];
  const void* c = d_in[1];
  const float2* pe;
  const float4* prm;
  if (in_sizes[0] > in_sizes[1]) { pe = (const float2*)a; prm = (const float4*)c; }
  else                           { pe = (const float2*)c; prm = (const float4*)a; }
  gr4j_3w<<<NBAS / 32, 96>>>(pe, prm, (float*)d_out);
}